// round 5
// baseline (speedup 1.0000x reference)
#include <cuda_runtime.h>
#include <math.h>
#include <stdint.h>

#define BB 8192
#define IND 512
#define HIDD 2048
#define NCLS 1000
#define NE 4

__device__ float d_partial[3 * 512];
__device__ unsigned char d_slot[NE * BB];
__device__ float d_gatew[BB * 2];
__device__ int   d_cnt[NE];
__device__ int   d_tok[NE * BB];
__device__ char  d_w1i[NE * HIDD * IND];
__device__ char  d_w2i[(size_t)NE * HIDD * HIDD];
__device__ char  d_w3i[(size_t)NE * 1024 * HIDD];   // rows 1000..1023 stay zero
__device__ short d_hraw[(size_t)NE * BB * HIDD];
__device__ char  d_a1[(size_t)NE * BB * HIDD];
__device__ char  d_a2[(size_t)NE * BB * HIDD];
__device__ short d_eo16[(size_t)BB * 2 * 1024];

// ---------------- weight mean (deterministic 2-pass) ----------------
__global__ __launch_bounds__(256) void k_reduce(const float* __restrict__ W, int n_per_e, int m) {
    int e = blockIdx.x >> 7, blk = blockIdx.x & 127;
    size_t base = (size_t)e * n_per_e;
    int chunk = (n_per_e + 127) >> 7;
    int s = blk * chunk, en = min(s + chunk, n_per_e);
    float acc = 0.f;
    for (int i = s + (int)threadIdx.x; i < en; i += 256) acc += W[base + i];
    __shared__ float red[256];
    red[threadIdx.x] = acc; __syncthreads();
    for (int st = 128; st > 0; st >>= 1) {
        if ((int)threadIdx.x < st) red[threadIdx.x] += red[threadIdx.x + st];
        __syncthreads();
    }
    if (threadIdx.x == 0) d_partial[m * 512 + blockIdx.x] = red[0];
}

// ---------------- weight pack -> int8 +-1 ----------------
__global__ __launch_bounds__(256) void k_packw(const float* __restrict__ W, int m, int ne_elems) {
    size_t idx = (size_t)blockIdx.x * 256;
    int e = (int)(idx / (size_t)ne_elems);
    __shared__ float red[128];
    int t = threadIdx.x;
    if (t < 128) red[t] = d_partial[m * 512 + e * 128 + t];
    __syncthreads();
    for (int st = 64; st > 0; st >>= 1) { if (t < st) red[t] += red[t + st]; __syncthreads(); }
    float mu = red[0] / (float)ne_elems;
    size_t i = idx + t;
    char v = (W[i] > mu) ? 1 : -1;
    if (m == 0) d_w1i[i] = v;
    else if (m == 1) d_w2i[i] = v;
    else d_w3i[(size_t)e * 1024 * HIDD + (i - (size_t)e * ne_elems)] = v;
}

// ---------------- fused router MLP + softmax + top2 ----------------
__global__ __launch_bounds__(256) void k_router(const float* __restrict__ x,
    const float* __restrict__ Wr1, const float* __restrict__ br1,
    const float* __restrict__ Wr2, const float* __restrict__ br2,
    const float* __restrict__ Wr3, const float* __restrict__ br3)
{
    __shared__ float buf[16 * 512];
    int b0 = blockIdx.x * 16, tid = threadIdx.x;
    for (int i = tid; i < 16 * 512; i += 256) buf[i] = x[(size_t)b0 * 512 + i];
    __syncthreads();
    float acc[16];
#pragma unroll
    for (int t = 0; t < 16; t++) acc[t] = 0.f;
    {
        const float* w = Wr1 + (size_t)tid * 512;
        for (int i = 0; i < 512; i++) {
            float wv = __ldg(w + i);
#pragma unroll
            for (int t = 0; t < 16; t++) acc[t] = fmaf(wv, buf[t * 512 + i], acc[t]);
        }
    }
    __syncthreads();
    {
        float bb = br1[tid];
#pragma unroll
        for (int t = 0; t < 16; t++) buf[t * 256 + tid] = fmaxf(acc[t] + bb, 0.f);
    }
    __syncthreads();
    if (tid < 128) {
#pragma unroll
        for (int t = 0; t < 16; t++) acc[t] = 0.f;
        const float* w = Wr2 + (size_t)tid * 256;
        for (int i = 0; i < 256; i++) {
            float wv = __ldg(w + i);
#pragma unroll
            for (int t = 0; t < 16; t++) acc[t] = fmaf(wv, buf[t * 256 + i], acc[t]);
        }
    }
    __syncthreads();
    if (tid < 128) {
        float bb = br2[tid];
#pragma unroll
        for (int t = 0; t < 16; t++) buf[4096 + t * 132 + tid] = fmaxf(acc[t] + bb, 0.f);
    }
    __syncthreads();
    if (tid < 16) {
        float s[4];
#pragma unroll
        for (int e = 0; e < 4; e++) {
            float a = br3[e];
            const float* w = Wr3 + e * 128;
            for (int i = 0; i < 128; i++) a = fmaf(w[i], buf[4096 + tid * 132 + i], a);
            s[e] = a;
        }
        float m = fmaxf(fmaxf(s[0], s[1]), fmaxf(s[2], s[3]));
        float p[4], Z = 0.f;
#pragma unroll
        for (int e = 0; e < 4; e++) { p[e] = expf(s[e] - m); Z += p[e]; }
        int i0 = 0;
        for (int e = 1; e < 4; e++) if (p[e] > p[i0]) i0 = e;
        int i1 = (i0 == 0) ? 1 : 0;
        for (int e = 0; e < 4; e++) { if (e == i0) continue; if (p[e] > p[i1]) i1 = e; }
        int b = b0 + tid;
        float g0 = p[i0] / Z, g1 = p[i1] / Z, gs = g0 + g1;
        d_gatew[b * 2] = g0 / gs; d_gatew[b * 2 + 1] = g1 / gs;
#pragma unroll
        for (int e = 0; e < 4; e++)
            d_slot[e * BB + b] = (e == i0) ? 0 : ((e == i1) ? 1 : 0xFF);
    }
}

// ---------------- deterministic per-expert compaction ----------------
__global__ __launch_bounds__(256) void k_compact() {
    int e = blockIdx.x, t = threadIdx.x;
    __shared__ int cnts[256];
    int base = t * 32, c = 0;
    for (int i = 0; i < 32; i++) if (d_slot[e * BB + base + i] != 0xFF) c++;
    cnts[t] = c; __syncthreads();
    for (int st = 1; st < 256; st <<= 1) {
        int v = (t >= st) ? cnts[t - st] : 0;
        __syncthreads();
        cnts[t] += v;
        __syncthreads();
    }
    int off = cnts[t] - c;
    for (int i = 0; i < 32; i++)
        if (d_slot[e * BB + base + i] != 0xFF) d_tok[e * BB + off++] = base + i;
    if (t == 255) d_cnt[e] = cnts[255];
}

// ---------------- int8 mma.sync GEMM ----------------
// mode1: A=sign(x) +-1 (from x, K=512), W1 -> d_hraw
// mode2: A=d_a1 {0,1} (K=2048), W2 -> d_hraw
// mode3: A=d_a2 (K=2048), W3 (1024 rows) -> d_eo16 (token/slot scatter)
#define PITCH 80
__device__ __forceinline__ void imma(int* c, const uint32_t* a, const uint32_t* b) {
    asm volatile("mma.sync.aligned.m16n8k32.row.col.s32.s8.s8.s32 "
                 "{%0,%1,%2,%3}, {%4,%5,%6,%7}, {%8,%9}, {%0,%1,%2,%3};"
                 : "+r"(c[0]), "+r"(c[1]), "+r"(c[2]), "+r"(c[3])
                 : "r"(a[0]), "r"(a[1]), "r"(a[2]), "r"(a[3]), "r"(b[0]), "r"(b[1]));
}
__device__ __forceinline__ uint32_t sgn4(float4 f) {
    return (f.x > 0.f ? 1u : 0xFFu) | ((f.y > 0.f ? 1u : 0xFFu) << 8)
         | ((f.z > 0.f ? 1u : 0xFFu) << 16) | ((f.w > 0.f ? 1u : 0xFFu) << 24);
}

__global__ __launch_bounds__(256) void k_mma(int mode, const float* __restrict__ x) {
    int e = blockIdx.z, m0 = blockIdx.x * 128, n0 = blockIdx.y * 128;
    int cnt = d_cnt[e];
    if (m0 >= cnt) return;
    int K = (mode == 1) ? IND : HIDD;
    const char* Wb = (mode == 1) ? d_w1i : (mode == 2 ? d_w2i : d_w3i);
    const char* Ab = (mode == 2) ? d_a1 : d_a2;
    int NROWS = (mode == 3) ? 1024 : HIDD;

    __shared__ char sm[2 * 2 * 128 * PITCH];   // [buf][A/B][128][80]
    int tid = threadIdx.x, wid = tid >> 5, lane = tid & 31;
    int g = lane >> 2, tig = lane & 3;
    int wm = wid & 1, wn = wid >> 1;           // 2 x 4 warp grid

    int lrow = tid >> 1, lpart = tid & 1;      // global->smem loader role
    const float* xrow = nullptr;
    const char* arow = nullptr;
    {
        int pos = m0 + lrow; if (pos > cnt - 1) pos = cnt - 1;
        if (mode == 1) xrow = x + (size_t)d_tok[e * BB + pos] * IND;
        else arow = Ab + ((size_t)e * BB + pos) * (size_t)K;
    }
    const char* brow = Wb + ((size_t)e * NROWS + n0 + lrow) * (size_t)K;

    int NC = K / 64;
    int acc[4][4][4];
#pragma unroll
    for (int i = 0; i < 4; i++)
#pragma unroll
        for (int j = 0; j < 4; j++)
#pragma unroll
            for (int q = 0; q < 4; q++) acc[i][j][q] = 0;

#define LOADCH(c, s)                                                            \
    {                                                                           \
        char* ab = sm + (s) * (2 * 128 * PITCH);                                \
        char* bb2 = ab + 128 * PITCH;                                           \
        if (mode == 1) {                                                        \
            const float4* p = (const float4*)(xrow + (c) * 64 + lpart * 32);    \
            uint4 v;                                                            \
            v.x = sgn4(p[0]); v.y = sgn4(p[1]); v.z = sgn4(p[2]); v.w = sgn4(p[3]); \
            *(uint4*)(ab + lrow * PITCH + lpart * 32) = v;                      \
            uint4 v2;                                                           \
            v2.x = sgn4(p[4]); v2.y = sgn4(p[5]); v2.z = sgn4(p[6]); v2.w = sgn4(p[7]); \
            *(uint4*)(ab + lrow * PITCH + lpart * 32 + 16) = v2;                \
        } else {                                                                \
            const uint4* p = (const uint4*)(arow + (c) * 64 + lpart * 32);      \
            *(uint4*)(ab + lrow * PITCH + lpart * 32) = p[0];                   \
            *(uint4*)(ab + lrow * PITCH + lpart * 32 + 16) = p[1];              \
        }                                                                       \
        const uint4* q = (const uint4*)(brow + (c) * 64 + lpart * 32);          \
        *(uint4*)(bb2 + lrow * PITCH + lpart * 32) = q[0];                      \
        *(uint4*)(bb2 + lrow * PITCH + lpart * 32 + 16) = q[1];                 \
    }

    LOADCH(0, 0);
    __syncthreads();
    for (int c = 0; c < NC; c++) {
        if (c + 1 < NC) LOADCH(c + 1, (c + 1) & 1);
        char* ab = sm + (c & 1) * (2 * 128 * PITCH);
        char* bb2 = ab + 128 * PITCH;
#pragma unroll
        for (int ks = 0; ks < 2; ks++) {
            int kk = ks * 32;
            uint32_t af[4][4], bf[4][2];
#pragma unroll
            for (int i = 0; i < 4; i++) {
                int r0 = wm * 64 + i * 16 + g;
                af[i][0] = *(const uint32_t*)(ab + r0 * PITCH + kk + tig * 4);
                af[i][1] = *(const uint32_t*)(ab + (r0 + 8) * PITCH + kk + tig * 4);
                af[i][2] = *(const uint32_t*)(ab + r0 * PITCH + kk + 16 + tig * 4);
                af[i][3] = *(const uint32_t*)(ab + (r0 + 8) * PITCH + kk + 16 + tig * 4);
            }
#pragma unroll
            for (int j = 0; j < 4; j++) {
                int cc = wn * 32 + j * 8 + g;
                bf[j][0] = *(const uint32_t*)(bb2 + cc * PITCH + kk + tig * 4);
                bf[j][1] = *(const uint32_t*)(bb2 + cc * PITCH + kk + 16 + tig * 4);
            }
#pragma unroll
            for (int i = 0; i < 4; i++)
#pragma unroll
                for (int j = 0; j < 4; j++) imma(acc[i][j], af[i], bf[j]);
        }
        __syncthreads();
    }
#undef LOADCH

    // epilogue: s32 -> packed short2 stores
#pragma unroll
    for (int i = 0; i < 4; i++) {
        int r0 = m0 + wm * 64 + i * 16 + g;
#pragma unroll
        for (int half = 0; half < 2; half++) {
            int r = r0 + half * 8;
            if (r >= cnt) continue;
            uint32_t* dst;
            if (mode == 3) {
                int tok = d_tok[e * BB + r];
                int sl = d_slot[e * BB + tok];
                dst = (uint32_t*)(d_eo16 + ((size_t)(tok * 2 + sl)) * 1024 + n0);
            } else {
                dst = (uint32_t*)(d_hraw + ((size_t)e * BB + r) * HIDD + n0);
            }
#pragma unroll
            for (int j = 0; j < 4; j++) {
                int col = wn * 32 + j * 8 + tig * 2;
                int v0 = acc[i][j][half * 2], v1 = acc[i][j][half * 2 + 1];
                dst[col >> 1] = ((uint32_t)(unsigned short)(short)v0)
                              | ((uint32_t)(unsigned short)(short)v1 << 16);
            }
        }
    }
}

// ---------------- LayerNorm + relu + sign -> int8 {0,1} (exact int stats) ----------------
__global__ __launch_bounds__(256) void k_ln(const float* __restrict__ g,
                                            const float* __restrict__ bt, int phase) {
    int e = blockIdx.y, pos = blockIdx.x;
    if (pos >= d_cnt[e]) return;
    const short* raw = d_hraw + ((size_t)e * BB + pos) * HIDD;
    int tid = threadIdx.x;
    __shared__ int s_i[256];
    __shared__ long long s_q[256];
    int v[8]; int isum = 0; long long isq = 0;
#pragma unroll
    for (int it = 0; it < 8; it++) {
        int h = raw[it * 256 + tid];
        v[it] = h; isum += h; isq += (long long)h * h;
    }
    s_i[tid] = isum; s_q[tid] = isq;
    __syncthreads();
    for (int st = 128; st > 0; st >>= 1) {
        if (tid < st) { s_i[tid] += s_i[tid + st]; s_q[tid] += s_q[tid + st]; }
        __syncthreads();
    }
    double mu = (double)s_i[0] / 2048.0;
    double var = (double)s_q[0] / 2048.0 - mu * mu;
    float rs = (float)(1.0 / sqrt(var + 1e-5));
    float fmu = (float)mu;
    char* dst = ((phase == 1) ? d_a1 : d_a2) + ((size_t)e * BB + pos) * HIDD;
#pragma unroll
    for (int it = 0; it < 8; it++) {
        int idx = it * 256 + tid;
        float hn = ((float)v[it] - fmu) * rs;
        dst[idx] = (hn * g[e * HIDD + idx] + bt[e * HIDD + idx]) > 0.f ? 1 : 0;
    }
}

// ---------------- gate combine ----------------
__global__ __launch_bounds__(256) void k_combine(float* __restrict__ out) {
    int i = blockIdx.x * 256 + threadIdx.x;
    if (i >= BB * NCLS) return;
    int b = i / NCLS, c = i - b * NCLS;
    out[i] = d_gatew[b * 2] * (float)d_eo16[(size_t)(b * 2) * 1024 + c]
           + d_gatew[b * 2 + 1] * (float)d_eo16[(size_t)(b * 2 + 1) * 1024 + c];
}

extern "C" void kernel_launch(void* const* d_in, const int* in_sizes, int n_in,
                              void* d_out, int out_size) {
    const float* x   = (const float*)d_in[0];
    const float* Wr1 = (const float*)d_in[1];
    const float* br1 = (const float*)d_in[2];
    const float* Wr2 = (const float*)d_in[3];
    const float* br2 = (const float*)d_in[4];
    const float* Wr3 = (const float*)d_in[5];
    const float* br3 = (const float*)d_in[6];
    const float* W1  = (const float*)d_in[7];
    const float* g1  = (const float*)d_in[8];
    const float* b1  = (const float*)d_in[9];
    const float* W2  = (const float*)d_in[10];
    const float* g2  = (const float*)d_in[11];
    const float* b2  = (const float*)d_in[12];
    const float* W3  = (const float*)d_in[13];
    float* out = (float*)d_out;

    k_reduce<<<512, 256>>>(W1, HIDD * IND, 0);                   // 0
    k_reduce<<<512, 256>>>(W2, HIDD * HIDD, 1);                  // 1
    k_packw<<<NE * HIDD * IND / 256, 256>>>(W1, 0, HIDD * IND);  // 2
    k_router<<<BB / 16, 256>>>(x, Wr1, br1, Wr2, br2, Wr3, br3); // 3
    k_compact<<<NE, 256>>>();                                    // 4
    k_mma<<<dim3(BB / 128, HIDD / 128, NE), 256>>>(1, x);        // 5 <- ncu window
    k_reduce<<<512, 256>>>(W3, NCLS * HIDD, 2);
    k_packw<<<NE * HIDD * HIDD / 256, 256>>>(W2, 1, HIDD * HIDD);
    k_packw<<<NE * NCLS * HIDD / 256, 256>>>(W3, 2, NCLS * HIDD);
    k_ln<<<dim3(BB, NE), 256>>>(g1, b1, 1);
    k_mma<<<dim3(BB / 128, HIDD / 128, NE), 256>>>(2, x);
    k_ln<<<dim3(BB, NE), 256>>>(g2, b2, 2);
    k_mma<<<dim3(BB / 128, 1024 / 128, NE), 256>>>(3, x);
    k_combine<<<(BB * NCLS + 255) / 256, 256>>>(out);
}

// round 6
// speedup vs baseline: 1.9006x; 1.9006x over previous
#include <cuda_runtime.h>
#include <math.h>
#include <stdint.h>

#define BB 8192
#define IND 512
#define HIDD 2048
#define NCLS 1000
#define NE 4
#define KW1 16
#define KW2 64

// ---------------- device scratch ----------------
__device__ unsigned d_xbits[BB * KW1];
__device__ unsigned d_w1b[NE * HIDD * KW1];
__device__ unsigned d_w2b[NE * HIDD * KW2];
__device__ unsigned d_w3b[NE * NCLS * KW2];
__device__ short    d_hraw[(size_t)NE * BB * HIDD];
__device__ unsigned d_h1bits[NE * BB * KW2];
__device__ unsigned d_h2bits[NE * BB * KW2];
__device__ int      d_apop1[NE * BB];
__device__ int      d_apop2[NE * BB];
__device__ short    d_eo[(size_t)BB * 2 * NCLS];
__device__ float    d_partial[3 * 512];
__device__ float    d_means[12];
__device__ float    d_gatew[BB * 2];
__device__ unsigned char d_slot[NE * BB];   // slot 0/1, 0xFF unselected
__device__ int      d_cnt[NE];
__device__ int      d_tok[NE * BB];
__device__ float    d_rh1[(size_t)BB * 256];
__device__ float    d_rh2[(size_t)BB * 128];

// ---------------- weight mean (deterministic 2-pass) ----------------
__global__ __launch_bounds__(256) void k_reduce(const float* __restrict__ W, int n_per_e, int m) {
    int e = blockIdx.x >> 7, blk = blockIdx.x & 127;
    size_t base = (size_t)e * n_per_e;
    int chunk = (n_per_e + 127) >> 7;
    int s = blk * chunk, en = min(s + chunk, n_per_e);
    float acc = 0.f;
    for (int i = s + (int)threadIdx.x; i < en; i += 256) acc += W[base + i];
    __shared__ float red[256];
    red[threadIdx.x] = acc; __syncthreads();
    for (int st = 128; st > 0; st >>= 1) {
        if ((int)threadIdx.x < st) red[threadIdx.x] += red[threadIdx.x + st];
        __syncthreads();
    }
    if (threadIdx.x == 0) d_partial[m * 512 + blockIdx.x] = red[0];
}

__global__ void k_means() {
    int t = threadIdx.x;
    if (t >= 12) return;
    int m = t >> 2, e = t & 3;
    float s = 0.f;
    for (int i = 0; i < 128; i++) s += d_partial[m * 512 + e * 128 + i];
    float n = (m == 0) ? 2048.f * 512.f : (m == 1 ? 2048.f * 2048.f : 1000.f * 2048.f);
    d_means[t] = s / n;
}

// ---------------- weight bit packing ----------------
__global__ __launch_bounds__(256) void k_packw(const float* __restrict__ W, int moff,
                                               int words_per_e, int target, int total) {
    int w = blockIdx.x * 256 + threadIdx.x;
    if (w >= total) return;
    int e = w / words_per_e;
    float mu = d_means[moff + e];
    const float* p = W + (size_t)w * 32;
    unsigned bits = 0;
#pragma unroll
    for (int j = 0; j < 32; j++) bits |= (p[j] > mu) ? (1u << j) : 0u;
    unsigned* out = (target == 0) ? d_w1b : (target == 1 ? d_w2b : d_w3b);
    out[w] = bits;
}

__global__ __launch_bounds__(256) void k_packx(const float* __restrict__ x) {
    int w = blockIdx.x * 256 + threadIdx.x;
    const float* p = x + (size_t)w * 32;
    unsigned bits = 0;
#pragma unroll
    for (int j = 0; j < 32; j++) bits |= (p[j] > 0.f) ? (1u << j) : 0u;
    d_xbits[w] = bits;
}

// ---------------- router: register-blocked fp32 GEMM + relu ----------------
// out[M x N] = relu(A[M x K] @ W[N x K]^T + bias), tiles 64x64, BK=16, 4x4/thread
__global__ __launch_bounds__(256) void k_rgemm(const float* __restrict__ A,
                                               const float* __restrict__ W,
                                               const float* __restrict__ bias,
                                               float* __restrict__ out, int K, int N) {
    int m0 = blockIdx.x * 64, n0 = blockIdx.y * 64;
    __shared__ float As[16][68];
    __shared__ float Bs[16][68];
    int tid = threadIdx.x;
    int lr = tid >> 2, lk = (tid & 3) * 4;
    int tx = tid & 15, ty = tid >> 4;
    const float* Arow = A + (size_t)(m0 + lr) * K + lk;
    const float* Wrow = W + (size_t)(n0 + lr) * K + lk;
    float4 pa = *(const float4*)Arow;
    float4 pb = *(const float4*)Wrow;
    float acc[4][4];
#pragma unroll
    for (int i = 0; i < 4; i++)
#pragma unroll
        for (int j = 0; j < 4; j++) acc[i][j] = 0.f;
    int NCH = K / 16;
    for (int c = 0; c < NCH; c++) {
        As[lk + 0][lr] = pa.x; As[lk + 1][lr] = pa.y; As[lk + 2][lr] = pa.z; As[lk + 3][lr] = pa.w;
        Bs[lk + 0][lr] = pb.x; Bs[lk + 1][lr] = pb.y; Bs[lk + 2][lr] = pb.z; Bs[lk + 3][lr] = pb.w;
        __syncthreads();
        if (c + 1 < NCH) {
            pa = *(const float4*)(Arow + (c + 1) * 16);
            pb = *(const float4*)(Wrow + (c + 1) * 16);
        }
#pragma unroll
        for (int kk = 0; kk < 16; kk++) {
            float4 a4 = *(const float4*)&As[kk][ty * 4];
            float4 b4 = *(const float4*)&Bs[kk][tx * 4];
            float av[4] = {a4.x, a4.y, a4.z, a4.w};
            float bv[4] = {b4.x, b4.y, b4.z, b4.w};
#pragma unroll
            for (int i = 0; i < 4; i++)
#pragma unroll
                for (int j = 0; j < 4; j++) acc[i][j] = fmaf(av[i], bv[j], acc[i][j]);
        }
        __syncthreads();
    }
#pragma unroll
    for (int i = 0; i < 4; i++) {
        float4 o4;
        float* r = &o4.x;
#pragma unroll
        for (int j = 0; j < 4; j++) r[j] = fmaxf(acc[i][j] + bias[n0 + tx * 4 + j], 0.f);
        *(float4*)&out[(size_t)(m0 + ty * 4 + i) * N + n0 + tx * 4] = o4;
    }
}

// ---------------- router head: scores + softmax + top2 ----------------
__global__ __launch_bounds__(128) void k_r3(const float* __restrict__ Wr3,
                                            const float* __restrict__ br3) {
    __shared__ float ws[512];
    __shared__ float bs[4];
    int tid = threadIdx.x;
    for (int i = tid; i < 512; i += 128) ws[i] = Wr3[i];
    if (tid < 4) bs[tid] = br3[tid];
    __syncthreads();
    int w = tid >> 5, l = tid & 31;
    int t = blockIdx.x * 4 + w;
    float h[4];
#pragma unroll
    for (int j = 0; j < 4; j++) h[j] = d_rh2[(size_t)t * 128 + l + 32 * j];
    float s[4];
#pragma unroll
    for (int e = 0; e < 4; e++) {
        float v = h[0] * ws[e * 128 + l] + h[1] * ws[e * 128 + l + 32]
                + h[2] * ws[e * 128 + l + 64] + h[3] * ws[e * 128 + l + 96];
#pragma unroll
        for (int off = 16; off > 0; off >>= 1) v += __shfl_xor_sync(0xffffffffu, v, off);
        s[e] = v + bs[e];
    }
    if (l == 0) {
        float m = fmaxf(fmaxf(s[0], s[1]), fmaxf(s[2], s[3]));
        float p[4], Z = 0.f;
#pragma unroll
        for (int e = 0; e < 4; e++) { p[e] = expf(s[e] - m); Z += p[e]; }
        int i0 = 0;
        for (int e = 1; e < 4; e++) if (p[e] > p[i0]) i0 = e;
        int i1 = (i0 == 0) ? 1 : 0;
        for (int e = 0; e < 4; e++) { if (e == i0) continue; if (p[e] > p[i1]) i1 = e; }
        float g0 = p[i0] / Z, g1 = p[i1] / Z, gs = g0 + g1;
        d_gatew[t * 2] = g0 / gs; d_gatew[t * 2 + 1] = g1 / gs;
#pragma unroll
        for (int e = 0; e < 4; e++)
            d_slot[e * BB + t] = (e == i0) ? 0 : ((e == i1) ? 1 : 0xFF);
    }
}

// ---------------- deterministic per-expert compaction ----------------
__global__ __launch_bounds__(256) void k_compact() {
    int e = blockIdx.x, t = threadIdx.x;
    __shared__ int cnts[256];
    int base = t * 32, c = 0;
    for (int i = 0; i < 32; i++) if (d_slot[e * BB + base + i] != 0xFF) c++;
    cnts[t] = c; __syncthreads();
    for (int st = 1; st < 256; st <<= 1) {
        int v = (t >= st) ? cnts[t - st] : 0;
        __syncthreads();
        cnts[t] += v;
        __syncthreads();
    }
    int off = cnts[t] - c;
    for (int i = 0; i < 32; i++)
        if (d_slot[e * BB + base + i] != 0xFF) d_tok[e * BB + off++] = base + i;
    if (t == 255) d_cnt[e] = cnts[255];
}

// ---------------- layer1 binary GEMM (xor-popc, compacted) ----------------
__global__ __launch_bounds__(256) void k_gemm1() {
    __shared__ uint4 as_[64 * 4];
    int b0 = blockIdx.x * 64, o0 = blockIdx.y * 128, e = blockIdx.z;
    int cnt = d_cnt[e];
    if (b0 >= cnt) return;
    int tid = threadIdx.x;
    {
        int row = tid >> 2, q = tid & 3;
        int pos = min(b0 + row, cnt - 1);
        int tok = d_tok[e * BB + pos];
        as_[tid] = ((const uint4*)d_xbits)[tok * 4 + q];
    }
    __syncthreads();
    int o = tid & 127, t0 = (tid >> 7) * 32;
    const uint4* wr = (const uint4*)(d_w1b + ((size_t)e * HIDD + o0 + o) * KW1);
    uint4 w0 = wr[0], w1 = wr[1], w2 = wr[2], w3 = wr[3];
    for (int t = t0; t < t0 + 32; t++) {
        if (b0 + t >= cnt) break;
        uint4 a0 = as_[t*4+0], a1 = as_[t*4+1], a2 = as_[t*4+2], a3 = as_[t*4+3];
        int c = __popc(a0.x^w0.x)+__popc(a0.y^w0.y)+__popc(a0.z^w0.z)+__popc(a0.w^w0.w)
              + __popc(a1.x^w1.x)+__popc(a1.y^w1.y)+__popc(a1.z^w1.z)+__popc(a1.w^w1.w)
              + __popc(a2.x^w2.x)+__popc(a2.y^w2.y)+__popc(a2.z^w2.z)+__popc(a2.w^w2.w)
              + __popc(a3.x^w3.x)+__popc(a3.y^w3.y)+__popc(a3.z^w3.z)+__popc(a3.w^w3.w);
        d_hraw[((size_t)e * BB + b0 + t) * HIDD + o0 + o] = (short)(512 - 2 * c);
    }
}

// ---------------- LayerNorm + relu + sign-pack (exact integer stats) ----------------
__global__ __launch_bounds__(256) void k_ln(const float* __restrict__ g,
                                            const float* __restrict__ bt, int phase) {
    int e = blockIdx.y, pos = blockIdx.x;
    if (pos >= d_cnt[e]) return;
    size_t row = (size_t)e * BB + pos;
    const short* raw = d_hraw + row * HIDD;
    int tid = threadIdx.x, lane = tid & 31, wp = tid >> 5;
    __shared__ int s_i[256];
    __shared__ long long s_q[256];
    __shared__ int spop;
    if (tid == 0) spop = 0;
    int v[8]; int isum = 0; long long isq = 0;
#pragma unroll
    for (int it = 0; it < 8; it++) {
        int idx = it * 256 + wp * 32 + lane;
        int h = raw[idx];
        v[it] = h; isum += h; isq += (long long)h * h;
    }
    s_i[tid] = isum; s_q[tid] = isq;
    __syncthreads();
    for (int st = 128; st > 0; st >>= 1) {
        if (tid < st) { s_i[tid] += s_i[tid + st]; s_q[tid] += s_q[tid + st]; }
        __syncthreads();
    }
    double mu = (double)s_i[0] / 2048.0;
    double var = (double)s_q[0] / 2048.0 - mu * mu;
    float rs = (float)(1.0 / sqrt(var + 1e-5));
    float fmu = (float)mu;
    unsigned* outb = (phase == 1) ? d_h1bits : d_h2bits;
    int* outp = (phase == 1) ? d_apop1 : d_apop2;
#pragma unroll
    for (int it = 0; it < 8; it++) {
        int idx = it * 256 + wp * 32 + lane;
        float hn = ((float)v[it] - fmu) * rs;
        bool pred = (hn * g[e * HIDD + idx] + bt[e * HIDD + idx]) > 0.f;
        unsigned w = __ballot_sync(0xffffffffu, pred);
        if (lane == 0) {
            outb[row * KW2 + it * 8 + wp] = w;
            atomicAdd(&spop, __popc(w));
        }
    }
    __syncthreads();
    if (tid == 0) outp[row] = spop;
}

// ---------------- layer2 GEMM (and-popc, compacted) ----------------
__global__ __launch_bounds__(256) void k_gemm2() {
    __shared__ uint4 a4s[64 * 16];
    __shared__ int ap[64];
    int b0 = blockIdx.x * 64, o0 = blockIdx.y * 128, e = blockIdx.z;
    int cnt = d_cnt[e];
    if (b0 >= cnt) return;
    int tid = threadIdx.x;
#pragma unroll
    for (int r = 0; r < 4; r++) {
        int idx = tid + 256 * r;
        int row = idx >> 4, q = idx & 15;
        int pos = min(b0 + row, cnt - 1);
        a4s[idx] = ((const uint4*)d_h1bits)[((size_t)e * BB + pos) * 16 + q];
    }
    if (tid < 64) ap[tid] = d_apop1[(size_t)e * BB + min(b0 + tid, cnt - 1)];
    __syncthreads();
    int o = tid & 127, t0 = (tid >> 7) * 32;
    uint4 wreg[16];
    const uint4* wr = (const uint4*)(d_w2b + ((size_t)e * HIDD + o0 + o) * KW2);
#pragma unroll
    for (int k = 0; k < 16; k++) wreg[k] = wr[k];
    for (int t = t0; t < t0 + 32; t++) {
        if (b0 + t >= cnt) break;
        int acc = 0;
#pragma unroll
        for (int k = 0; k < 16; k++) {
            uint4 av = a4s[t * 16 + k];
            acc += __popc(av.x & wreg[k].x) + __popc(av.y & wreg[k].y)
                 + __popc(av.z & wreg[k].z) + __popc(av.w & wreg[k].w);
        }
        d_hraw[((size_t)e * BB + b0 + t) * HIDD + o0 + o] = (short)(2 * acc - ap[t]);
    }
}

// ---------------- layer3 GEMM -> per-slot dots (compacted, scatter) ----------------
__global__ __launch_bounds__(256) void k_gemm3() {
    __shared__ uint4 a4s[64 * 16];
    __shared__ int ap[64];
    __shared__ int ts[64];
    __shared__ unsigned char ss[64];
    int b0 = blockIdx.x * 64, c0 = blockIdx.y * 128, e = blockIdx.z;
    int cnt = d_cnt[e];
    if (b0 >= cnt) return;
    int tid = threadIdx.x;
#pragma unroll
    for (int r = 0; r < 4; r++) {
        int idx = tid + 256 * r;
        int row = idx >> 4, q = idx & 15;
        int pos = min(b0 + row, cnt - 1);
        a4s[idx] = ((const uint4*)d_h2bits)[((size_t)e * BB + pos) * 16 + q];
    }
    if (tid < 64) {
        int pos = min(b0 + tid, cnt - 1);
        ap[tid] = d_apop2[(size_t)e * BB + pos];
        int tok = d_tok[e * BB + pos];
        ts[tid] = tok;
        ss[tid] = d_slot[e * BB + tok];
    }
    __syncthreads();
    int c = c0 + (tid & 127), t0 = (tid >> 7) * 32;
    if (c >= NCLS) return;
    uint4 wreg[16];
    const uint4* wr = (const uint4*)(d_w3b + ((size_t)e * NCLS + c) * KW2);
#pragma unroll
    for (int k = 0; k < 16; k++) wreg[k] = wr[k];
    for (int t = t0; t < t0 + 32; t++) {
        if (b0 + t >= cnt) break;
        int acc = 0;
#pragma unroll
        for (int k = 0; k < 16; k++) {
            uint4 av = a4s[t * 16 + k];
            acc += __popc(av.x & wreg[k].x) + __popc(av.y & wreg[k].y)
                 + __popc(av.z & wreg[k].z) + __popc(av.w & wreg[k].w);
        }
        d_eo[((size_t)(ts[t] * 2 + ss[t])) * NCLS + c] = (short)(2 * acc - ap[t]);
    }
}

// ---------------- gate combine ----------------
__global__ __launch_bounds__(256) void k_combine(float* __restrict__ out) {
    int i = blockIdx.x * 256 + threadIdx.x;
    if (i >= BB * NCLS) return;
    int b = i / NCLS, c = i - b * NCLS;
    out[i] = d_gatew[b * 2] * (float)d_eo[(size_t)(b * 2) * NCLS + c]
           + d_gatew[b * 2 + 1] * (float)d_eo[(size_t)(b * 2 + 1) * NCLS + c];
}

extern "C" void kernel_launch(void* const* d_in, const int* in_sizes, int n_in,
                              void* d_out, int out_size) {
    const float* x   = (const float*)d_in[0];
    const float* Wr1 = (const float*)d_in[1];
    const float* br1 = (const float*)d_in[2];
    const float* Wr2 = (const float*)d_in[3];
    const float* br2 = (const float*)d_in[4];
    const float* Wr3 = (const float*)d_in[5];
    const float* br3 = (const float*)d_in[6];
    const float* W1  = (const float*)d_in[7];
    const float* g1  = (const float*)d_in[8];
    const float* b1  = (const float*)d_in[9];
    const float* W2  = (const float*)d_in[10];
    const float* g2  = (const float*)d_in[11];
    const float* b2  = (const float*)d_in[12];
    const float* W3  = (const float*)d_in[13];
    float* out = (float*)d_out;

    float* rh1; cudaGetSymbolAddress((void**)&rh1, d_rh1);
    float* rh2; cudaGetSymbolAddress((void**)&rh2, d_rh2);

    k_reduce<<<512, 256>>>(W1, HIDD * IND, 0);                    // 0
    k_reduce<<<512, 256>>>(W2, HIDD * HIDD, 1);                   // 1
    k_reduce<<<512, 256>>>(W3, NCLS * HIDD, 2);                   // 2
    k_rgemm<<<dim3(BB / 64, 4), 256>>>(x, Wr1, br1, rh1, 512, 256); // 3 <- ncu
    k_means<<<1, 32>>>();                                         // 4
    k_packw<<<(NE * HIDD * KW1 + 255) / 256, 256>>>(W1, 0, HIDD * KW1, 0, NE * HIDD * KW1);
    k_packw<<<(NE * HIDD * KW2 + 255) / 256, 256>>>(W2, 4, HIDD * KW2, 1, NE * HIDD * KW2);
    k_packw<<<(NE * NCLS * KW2 + 255) / 256, 256>>>(W3, 8, NCLS * KW2, 2, NE * NCLS * KW2);
    k_packx<<<(BB * KW1 + 255) / 256, 256>>>(x);
    k_rgemm<<<dim3(BB / 64, 2), 256>>>(rh1, Wr2, br2, rh2, 256, 128);
    k_r3<<<BB / 4, 128>>>(Wr3, br3);
    k_compact<<<NE, 256>>>();
    k_gemm1<<<dim3(BB / 64, HIDD / 128, NE), 256>>>();
    k_ln<<<dim3(BB, NE), 256>>>(g1, b1, 1);
    k_gemm2<<<dim3(BB / 64, HIDD / 128, NE), 256>>>();
    k_ln<<<dim3(BB, NE), 256>>>(g2, b2, 2);
    k_gemm3<<<dim3(BB / 64, (NCLS + 127) / 128, NE), 256>>>();
    k_combine<<<(BB * NCLS + 255) / 256, 256>>>(out);
}